// round 1
// baseline (speedup 1.0000x reference)
#include <cuda_runtime.h>
#include <math.h>

// Problem constants (shape-specialized)
#define T_TOK   2048
#define DIMX    2048
#define NH      32
#define NKV     8
#define HD      64
#define QKVC    3072      // (32 + 2*8) * 64
#define WIN     128
#define TQ      16        // query tokens per attention CTA
#define KROWS   143       // TQ + WIN - 1

// Scratch (no allocs allowed)
__device__ float g_qkv[(size_t)T_TOK * QKVC];   // 25.2 MB
__device__ float g_attn[(size_t)T_TOK * DIMX];  // 16.8 MB

// ---------------------------------------------------------------------------
// SGEMM: C[M,N] = A[M,K] * B[N,K]^T + bias[N]   (A,B row-major, K contiguous)
// 128x128 tile, BK=16, 256 threads, 8x8 microtile.
// ---------------------------------------------------------------------------
__global__ __launch_bounds__(256, 2)
void sgemm_nt(const float* __restrict__ A, const float* __restrict__ B,
              const float* __restrict__ bias, float* __restrict__ C,
              int M, int N, int K)
{
    __shared__ float As[16][132];
    __shared__ float Bs[16][132];

    const int tid     = threadIdx.x;
    const int rowBase = (tid >> 4) << 3;   // 0..120 step 8
    const int colBase = (tid & 15) << 3;   // 0..120 step 8

    const float* Ab = A + (size_t)(blockIdx.y * 128) * K;
    const float* Bb = B + (size_t)(blockIdx.x * 128) * K;

    float acc[8][8];
#pragma unroll
    for (int i = 0; i < 8; i++)
#pragma unroll
        for (int j = 0; j < 8; j++) acc[i][j] = 0.f;

    for (int k0 = 0; k0 < K; k0 += 16) {
#pragma unroll
        for (int l = 0; l < 2; l++) {
            int fid = tid + (l << 8);
            int row = fid >> 2;
            int kc  = (fid & 3) << 2;
            float4 av = *(const float4*)(Ab + (size_t)row * K + k0 + kc);
            As[kc + 0][row] = av.x; As[kc + 1][row] = av.y;
            As[kc + 2][row] = av.z; As[kc + 3][row] = av.w;
            float4 bv = *(const float4*)(Bb + (size_t)row * K + k0 + kc);
            Bs[kc + 0][row] = bv.x; Bs[kc + 1][row] = bv.y;
            Bs[kc + 2][row] = bv.z; Bs[kc + 3][row] = bv.w;
        }
        __syncthreads();

#pragma unroll
        for (int kk = 0; kk < 16; kk++) {
            float a[8], b[8];
            float4 a0 = *(const float4*)&As[kk][rowBase];
            float4 a1 = *(const float4*)&As[kk][rowBase + 4];
            float4 b0 = *(const float4*)&Bs[kk][colBase];
            float4 b1 = *(const float4*)&Bs[kk][colBase + 4];
            a[0]=a0.x; a[1]=a0.y; a[2]=a0.z; a[3]=a0.w;
            a[4]=a1.x; a[5]=a1.y; a[6]=a1.z; a[7]=a1.w;
            b[0]=b0.x; b[1]=b0.y; b[2]=b0.z; b[3]=b0.w;
            b[4]=b1.x; b[5]=b1.y; b[6]=b1.z; b[7]=b1.w;
#pragma unroll
            for (int i = 0; i < 8; i++)
#pragma unroll
                for (int j = 0; j < 8; j++)
                    acc[i][j] += a[i] * b[j];
        }
        __syncthreads();
    }

    const int gr = blockIdx.y * 128 + rowBase;
    const int gc = blockIdx.x * 128 + colBase;
    float bb[8];
#pragma unroll
    for (int j = 0; j < 8; j++) bb[j] = bias[gc + j];
#pragma unroll
    for (int i = 0; i < 8; i++) {
        float4 r0, r1;
        r0.x = acc[i][0] + bb[0]; r0.y = acc[i][1] + bb[1];
        r0.z = acc[i][2] + bb[2]; r0.w = acc[i][3] + bb[3];
        r1.x = acc[i][4] + bb[4]; r1.y = acc[i][5] + bb[5];
        r1.z = acc[i][6] + bb[6]; r1.w = acc[i][7] + bb[7];
        *(float4*)(C + (size_t)(gr + i) * N + gc)     = r0;
        *(float4*)(C + (size_t)(gr + i) * N + gc + 4) = r1;
    }
}

// ---------------------------------------------------------------------------
// RoPE in-place on q (channels [0,2048)) and k ([2048,2560)) of g_qkv.
// pair (d, d+32) within each 64-dim head.
// ---------------------------------------------------------------------------
__global__ void rope_kernel(const float* __restrict__ cosT,
                            const float* __restrict__ sinT)
{
    const int t = blockIdx.x;
    float* row = g_qkv + (size_t)t * QKVC;
    const float* ct = cosT + t * 64;
    const float* st = sinT + t * 64;
    for (int p = threadIdx.x; p < 40 * 32; p += blockDim.x) {
        int hh = p >> 5;          // 0..39  (32 q heads then 8 k heads)
        int dl = p & 31;
        int base = (hh < 32) ? hh * 64 : 2048 + (hh - 32) * 64;
        float lo = row[base + dl];
        float hi = row[base + dl + 32];
        float c0 = ct[dl],      s0 = st[dl];
        float c1 = ct[dl + 32], s1 = st[dl + 32];
        row[base + dl]      = lo * c0 - hi * s0;
        row[base + dl + 32] = hi * c1 + lo * s1;
    }
}

// ---------------------------------------------------------------------------
// Sliding-window attention with sink.
// CTA = (16-query tile, kv head). 256 threads.
// smem: Kt[64][144] (transposed K), V[144][64], Qt[64][64] (transposed Q,
// pre-scaled), S[64][129] scores, den[64].
// Row r = 4*i + g  (i = local query, g = group within kv head).
// For query t = t0+i, window slot w (0..127) maps to key u = i + w,
// global key j = t - 127 + w; invalid iff j < 0.
// ---------------------------------------------------------------------------
#define ATTN_SMEM_FLOATS (64*144 + 144*64 + 64*64 + 64*129 + 64)

__global__ __launch_bounds__(256, 1)
void swa_kernel(const float* __restrict__ sinks)
{
    extern __shared__ float sm[];
    float* Kt  = sm;                    // [64][144]
    float* V   = Kt + 64 * 144;        // [144][64]
    float* Qt  = V  + 144 * 64;        // [64][64]
    float* S   = Qt + 64 * 64;         // [64][129]
    float* den = S  + 64 * 129;        // [64]

    const int tid = threadIdx.x;
    const int t0  = blockIdx.x * TQ;
    const int kvh = blockIdx.y;

    // ---- load K (transposed) and V; zero-fill j<0 ----
    for (int idx = tid; idx < KROWS * 64; idx += 256) {
        int u = idx >> 6, d = idx & 63;
        int j = t0 - 127 + u;
        float kv = 0.f, vv = 0.f;
        if (j >= 0) {
            const float* r = g_qkv + (size_t)j * QKVC;
            kv = r[2048 + kvh * 64 + d];
            vv = r[2560 + kvh * 64 + d];
        }
        Kt[d * 144 + u] = kv;
        V[u * 64 + d]   = vv;
    }
    // ---- load Q transposed, pre-scaled by D^-0.5 = 0.125 ----
    for (int idx = tid; idx < 64 * 64; idx += 256) {
        int r = idx >> 6, d = idx & 63;
        int i = r >> 2, g = r & 3;
        Qt[d * 64 + r] =
            g_qkv[(size_t)(t0 + i) * QKVC + (kvh * 4 + g) * 64 + d] * 0.125f;
    }
    __syncthreads();

    // ---- scores: each thread does 2 tiles of 4 rows(g) x 4 window slots ----
    {
        const int c = tid & 31;
#pragma unroll
        for (int half = 0; half < 2; half++) {
            const int a = (tid >> 5) + half * 8;   // a == i (row group)
            float acc[16];
#pragma unroll
            for (int z = 0; z < 16; z++) acc[z] = 0.f;
#pragma unroll 8
            for (int d = 0; d < 64; d++) {
                float q0 = Qt[d * 64 + 4 * a + 0];
                float q1 = Qt[d * 64 + 4 * a + 1];
                float q2 = Qt[d * 64 + 4 * a + 2];
                float q3 = Qt[d * 64 + 4 * a + 3];
                float k0 = Kt[d * 144 + a + c];
                float k1 = Kt[d * 144 + a + c + 32];
                float k2 = Kt[d * 144 + a + c + 64];
                float k3 = Kt[d * 144 + a + c + 96];
                acc[0]  += q0 * k0; acc[1]  += q0 * k1; acc[2]  += q0 * k2; acc[3]  += q0 * k3;
                acc[4]  += q1 * k0; acc[5]  += q1 * k1; acc[6]  += q1 * k2; acc[7]  += q1 * k3;
                acc[8]  += q2 * k0; acc[9]  += q2 * k1; acc[10] += q2 * k2; acc[11] += q2 * k3;
                acc[12] += q3 * k0; acc[13] += q3 * k1; acc[14] += q3 * k2; acc[15] += q3 * k3;
            }
#pragma unroll
            for (int g = 0; g < 4; g++)
#pragma unroll
                for (int kk = 0; kk < 4; kk++)
                    S[(4 * a + g) * 129 + c + kk * 32] = acc[g * 4 + kk];
        }
    }
    __syncthreads();

    // ---- softmax per row (warp per row, 8 rows per warp), with sink ----
    {
        const int warp = tid >> 5, lane = tid & 31;
        for (int rr = 0; rr < 8; rr++) {
            int r = warp * 8 + rr;
            int i = r >> 2, g = r & 3;
            int t = t0 + i;
            int wmin = 127 - t;          // w < wmin -> key index j<0 (invalid)
            float s[4];
#pragma unroll
            for (int kk = 0; kk < 4; kk++) {
                int w = lane + kk * 32;
                float v = S[r * 129 + w];
                s[kk] = (w < wmin) ? -1e30f : v;
            }
            float m = fmaxf(fmaxf(s[0], s[1]), fmaxf(s[2], s[3]));
#pragma unroll
            for (int o = 16; o; o >>= 1)
                m = fmaxf(m, __shfl_xor_sync(0xffffffffu, m, o));
            float snk = __ldg(&sinks[kvh * 4 + g]);
            m = fmaxf(m, snk);
            float sum = 0.f;
#pragma unroll
            for (int kk = 0; kk < 4; kk++) {
                float e = __expf(s[kk] - m);
                S[r * 129 + lane + kk * 32] = e;
                sum += e;
            }
#pragma unroll
            for (int o = 16; o; o >>= 1)
                sum += __shfl_xor_sync(0xffffffffu, sum, o);
            sum += __expf(snk - m);
            if (lane == 0) den[r] = 1.0f / sum;
        }
    }
    __syncthreads();

    // ---- PV: thread tile 4 rows(g, fixed i=b) x 4 dims ----
    {
        const int b = tid >> 4;       // i = local query
        const int e = tid & 15;       // dim group
        float o_[4][4];
#pragma unroll
        for (int g = 0; g < 4; g++)
#pragma unroll
            for (int z = 0; z < 4; z++) o_[g][z] = 0.f;

        for (int w = 0; w < 128; w++) {
            float4 v4 = *(const float4*)(V + (b + w) * 64 + e * 4);
#pragma unroll
            for (int g = 0; g < 4; g++) {
                float p = S[(4 * b + g) * 129 + w];
                o_[g][0] += p * v4.x;
                o_[g][1] += p * v4.y;
                o_[g][2] += p * v4.z;
                o_[g][3] += p * v4.w;
            }
        }
        const int t = t0 + b;
#pragma unroll
        for (int g = 0; g < 4; g++) {
            float inv = den[4 * b + g];
            float4 r;
            r.x = o_[g][0] * inv; r.y = o_[g][1] * inv;
            r.z = o_[g][2] * inv; r.w = o_[g][3] * inv;
            *(float4*)(g_attn + (size_t)t * DIMX + (kvh * 4 + g) * 64 + e * 4) = r;
        }
    }
}

// ---------------------------------------------------------------------------
// kernel_launch
// inputs: x, cos, sin, Wqkv, bqkv, Wo, bo, sinks, window
// ---------------------------------------------------------------------------
extern "C" void kernel_launch(void* const* d_in, const int* in_sizes, int n_in,
                              void* d_out, int out_size)
{
    (void)in_sizes; (void)n_in; (void)out_size;
    const float* x     = (const float*)d_in[0];
    const float* cosT  = (const float*)d_in[1];
    const float* sinT  = (const float*)d_in[2];
    const float* Wqkv  = (const float*)d_in[3];
    const float* bqkv  = (const float*)d_in[4];
    const float* Wo    = (const float*)d_in[5];
    const float* bo    = (const float*)d_in[6];
    const float* sinks = (const float*)d_in[7];
    float* out = (float*)d_out;

    float* qkv = nullptr;
    float* att = nullptr;
    cudaGetSymbolAddress((void**)&qkv, g_qkv);
    cudaGetSymbolAddress((void**)&att, g_attn);

    const int attn_smem = ATTN_SMEM_FLOATS * 4;
    cudaFuncSetAttribute(swa_kernel,
                         cudaFuncAttributeMaxDynamicSharedMemorySize, attn_smem);

    // 1) qkv = x @ Wqkv^T + bqkv
    sgemm_nt<<<dim3(QKVC / 128, T_TOK / 128), 256>>>(
        x, Wqkv, bqkv, qkv, T_TOK, QKVC, DIMX);
    // 2) RoPE in-place on q,k
    rope_kernel<<<T_TOK, 256>>>(cosT, sinT);
    // 3) sliding-window attention with sink
    swa_kernel<<<dim3(T_TOK / TQ, NKV), 256, attn_smem>>>(sinks);
    // 4) out = attn @ Wo^T + bo
    sgemm_nt<<<dim3(DIMX / 128, T_TOK / 128), 256>>>(
        att, Wo, bo, out, T_TOK, DIMX, DIMX);
}

// round 4
// speedup vs baseline: 2.5493x; 2.5493x over previous
#include <cuda_runtime.h>
#include <math.h>
#include <cstdint>
#include <cstddef>

// ---------------- problem constants ----------------
#define T_TOK   2048
#define DIMX    2048
#define QKVC    3072      // (32 + 2*8) * 64
#define NKV     8
#define WIN     128
#define TQ      16
#define KROWS   143

// Scratch (no allocs allowed)
__device__ float g_qkv[(size_t)T_TOK * QKVC];
__device__ float g_attn[(size_t)T_TOK * DIMX];

// ---------------- helpers ----------------
__device__ __forceinline__ uint32_t smem_u32(const void* p) {
    uint32_t a;
    asm("{ .reg .u64 t; cvta.to.shared.u64 t, %1; cvt.u32.u64 %0, t; }"
        : "=r"(a) : "l"(p));
    return a;
}
__device__ __forceinline__ uint32_t f2tf32(float f) {
    uint32_t r;
    asm("cvt.rna.tf32.f32 %0, %1;" : "=r"(r) : "f"(f));
    return r;
}
__device__ __forceinline__ void mma_tf32(float* d, const uint32_t* a,
                                         const uint32_t* b) {
    asm volatile(
        "mma.sync.aligned.m16n8k8.row.col.f32.tf32.tf32.f32 "
        "{%0,%1,%2,%3}, {%4,%5,%6,%7}, {%8,%9}, {%0,%1,%2,%3};"
        : "+f"(d[0]), "+f"(d[1]), "+f"(d[2]), "+f"(d[3])
        : "r"(a[0]), "r"(a[1]), "r"(a[2]), "r"(a[3]), "r"(b[0]), "r"(b[1]));
}

// ---------------- tf32 mma.sync GEMM ----------------
// C[M, Ntot] = A[M, K] * B[Ntot, K]^T + bias   (A, B row-major, K contiguous)
// CTA tile 128x128x32, 3-stage cp.async pipeline, 256 threads.
#define GBM 128
#define GBN 128
#define GBK 32
#define PADW 36                    // floats per smem row (conflict-free frags)
#define SSTG (GBM * PADW * 2)      // floats per stage (A + B) = 9216
#define GEMM_SMEM (3 * SSTG * 4)   // 110592 bytes

__global__ __launch_bounds__(256, 1)
void gemm_mma_tf32(const float* __restrict__ A, const float* __restrict__ B,
                   const float* __restrict__ bias, float* __restrict__ C,
                   int Ntot, int K)
{
    extern __shared__ float smf[];
    const uint32_t sbase = smem_u32(smf);

    const int tid  = threadIdx.x;
    const int lane = tid & 31;
    const int wid  = tid >> 5;
    const int warpM = wid & 3;       // 4 warps along M (32 rows each)
    const int warpN = wid >> 2;      // 2 warps along N (64 cols each)
    const int gid = lane >> 2;       // groupID 0..7
    const int tig = lane & 3;        // thread-in-group 0..3

    const int m0 = blockIdx.y * GBM;
    const int n0 = blockIdx.x * GBN;
    const int niter = K / GBK;       // 64

    const float* Ag = A + (size_t)m0 * K;
    const float* Bg = B + (size_t)n0 * K;

    const int r0 = tid >> 3;         // 0..31
    const int c4 = (tid & 7) * 4;    // 0..28

    float acc[2][8][4];
#pragma unroll
    for (int mt = 0; mt < 2; mt++)
#pragma unroll
        for (int nt = 0; nt < 8; nt++)
#pragma unroll
            for (int z = 0; z < 4; z++) acc[mt][nt][z] = 0.f;

    // ---- async copy of one k-chunk into stage s ----
    auto issue = [&](int kt, int s) {
        if (kt < niter) {
            uint32_t abase = sbase + (uint32_t)(s * SSTG + r0 * PADW + c4) * 4;
            const float* ap = Ag + (size_t)r0 * K + kt * GBK + c4;
            const float* bp = Bg + (size_t)r0 * K + kt * GBK + c4;
            uint32_t bbase = abase + GBM * PADW * 4;
#pragma unroll
            for (int i = 0; i < 4; i++) {
                asm volatile("cp.async.cg.shared.global [%0], [%1], 16;"
                             :: "r"(abase + i * 32 * PADW * 4),
                                "l"(ap + (size_t)i * 32 * K) : "memory");
                asm volatile("cp.async.cg.shared.global [%0], [%1], 16;"
                             :: "r"(bbase + i * 32 * PADW * 4),
                                "l"(bp + (size_t)i * 32 * K) : "memory");
            }
        }
        asm volatile("cp.async.commit_group;" ::: "memory");
    };

    issue(0, 0);
    issue(1, 1);

    for (int it = 0; it < niter; it++) {
        asm volatile("cp.async.wait_group 1;" ::: "memory");
        __syncthreads();

        const int s = it % 3;
        const float* As = smf + s * SSTG;
        const float* Bs = As + GBM * PADW;

#pragma unroll
        for (int ks = 0; ks < 4; ks++) {
            const int k = ks * 8;
            uint32_t afr[2][4];
#pragma unroll
            for (int mt = 0; mt < 2; mt++) {
                int row = warpM * 32 + mt * 16 + gid;
                afr[mt][0] = f2tf32(As[row * PADW + k + tig]);
                afr[mt][1] = f2tf32(As[(row + 8) * PADW + k + tig]);
                afr[mt][2] = f2tf32(As[row * PADW + k + tig + 4]);
                afr[mt][3] = f2tf32(As[(row + 8) * PADW + k + tig + 4]);
            }
            uint32_t bfr[8][2];
#pragma unroll
            for (int nt = 0; nt < 8; nt++) {
                int col = warpN * 64 + nt * 8 + gid;
                bfr[nt][0] = f2tf32(Bs[col * PADW + k + tig]);
                bfr[nt][1] = f2tf32(Bs[col * PADW + k + tig + 4]);
            }
#pragma unroll
            for (int mt = 0; mt < 2; mt++)
#pragma unroll
                for (int nt = 0; nt < 8; nt++)
                    mma_tf32(acc[mt][nt], afr[mt], bfr[nt]);
        }
        __syncthreads();
        issue(it + 2, (it + 2) % 3);
    }

    // ---- epilogue ----
#pragma unroll
    for (int mt = 0; mt < 2; mt++) {
        int row = m0 + warpM * 32 + mt * 16 + gid;
#pragma unroll
        for (int nt = 0; nt < 8; nt++) {
            int col = n0 + warpN * 64 + nt * 8 + 2 * tig;
            float b0 = __ldg(&bias[col]);
            float b1 = __ldg(&bias[col + 1]);
            float2 v0 = make_float2(acc[mt][nt][0] + b0, acc[mt][nt][1] + b1);
            float2 v1 = make_float2(acc[mt][nt][2] + b0, acc[mt][nt][3] + b1);
            *(float2*)(C + (size_t)row * Ntot + col) = v0;
            *(float2*)(C + (size_t)(row + 8) * Ntot + col) = v1;
        }
    }
}

// ---------------- RoPE ----------------
__global__ void rope_kernel(const float* __restrict__ cosT,
                            const float* __restrict__ sinT)
{
    const int t = blockIdx.x;
    float* row = g_qkv + (size_t)t * QKVC;
    const float* ct = cosT + t * 64;
    const float* st = sinT + t * 64;
    for (int p = threadIdx.x; p < 40 * 32; p += blockDim.x) {
        int hh = p >> 5;
        int dl = p & 31;
        int base = (hh < 32) ? hh * 64 : 2048 + (hh - 32) * 64;
        float lo = row[base + dl];
        float hi = row[base + dl + 32];
        float c0 = ct[dl],      s0 = st[dl];
        float c1 = ct[dl + 32], s1 = st[dl + 32];
        row[base + dl]      = lo * c0 - hi * s0;
        row[base + dl + 32] = hi * c1 + lo * s1;
    }
}

// ---------------- SWA ----------------
#define ATTN_SMEM_FLOATS (64*144 + 144*64 + 64*64 + 64*129 + 64)

__global__ __launch_bounds__(256, 1)
void swa_kernel(const float* __restrict__ sinks)
{
    extern __shared__ float sm[];
    float* Kt  = sm;
    float* V   = Kt + 64 * 144;
    float* Qt  = V  + 144 * 64;
    float* S   = Qt + 64 * 64;
    float* den = S  + 64 * 129;

    const int tid = threadIdx.x;
    const int t0  = blockIdx.x * TQ;
    const int kvh = blockIdx.y;

    for (int idx = tid; idx < KROWS * 64; idx += 256) {
        int u = idx >> 6, d = idx & 63;
        int j = t0 - 127 + u;
        float kv = 0.f, vv = 0.f;
        if (j >= 0) {
            const float* r = g_qkv + (size_t)j * QKVC;
            kv = r[2048 + kvh * 64 + d];
            vv = r[2560 + kvh * 64 + d];
        }
        Kt[d * 144 + u] = kv;
        V[u * 64 + d]   = vv;
    }
    for (int idx = tid; idx < 64 * 64; idx += 256) {
        int r = idx >> 6, d = idx & 63;
        int i = r >> 2, g = r & 3;
        Qt[d * 64 + r] =
            g_qkv[(size_t)(t0 + i) * QKVC + (kvh * 4 + g) * 64 + d] * 0.125f;
    }
    __syncthreads();

    {
        const int c = tid & 31;
#pragma unroll
        for (int half = 0; half < 2; half++) {
            const int a = (tid >> 5) + half * 8;
            float acc[16];
#pragma unroll
            for (int z = 0; z < 16; z++) acc[z] = 0.f;
#pragma unroll 8
            for (int d = 0; d < 64; d++) {
                float q0 = Qt[d * 64 + 4 * a + 0];
                float q1 = Qt[d * 64 + 4 * a + 1];
                float q2 = Qt[d * 64 + 4 * a + 2];
                float q3 = Qt[d * 64 + 4 * a + 3];
                float k0 = Kt[d * 144 + a + c];
                float k1 = Kt[d * 144 + a + c + 32];
                float k2 = Kt[d * 144 + a + c + 64];
                float k3 = Kt[d * 144 + a + c + 96];
                acc[0]  += q0 * k0; acc[1]  += q0 * k1; acc[2]  += q0 * k2; acc[3]  += q0 * k3;
                acc[4]  += q1 * k0; acc[5]  += q1 * k1; acc[6]  += q1 * k2; acc[7]  += q1 * k3;
                acc[8]  += q2 * k0; acc[9]  += q2 * k1; acc[10] += q2 * k2; acc[11] += q2 * k3;
                acc[12] += q3 * k0; acc[13] += q3 * k1; acc[14] += q3 * k2; acc[15] += q3 * k3;
            }
#pragma unroll
            for (int g = 0; g < 4; g++)
#pragma unroll
                for (int kk = 0; kk < 4; kk++)
                    S[(4 * a + g) * 129 + c + kk * 32] = acc[g * 4 + kk];
        }
    }
    __syncthreads();

    {
        const int warp = tid >> 5, lane = tid & 31;
        for (int rr = 0; rr < 8; rr++) {
            int r = warp * 8 + rr;
            int i = r >> 2, g = r & 3;
            int t = t0 + i;
            int wmin = 127 - t;
            float s[4];
#pragma unroll
            for (int kk = 0; kk < 4; kk++) {
                int w = lane + kk * 32;
                float v = S[r * 129 + w];
                s[kk] = (w < wmin) ? -1e30f : v;
            }
            float m = fmaxf(fmaxf(s[0], s[1]), fmaxf(s[2], s[3]));
#pragma unroll
            for (int o = 16; o; o >>= 1)
                m = fmaxf(m, __shfl_xor_sync(0xffffffffu, m, o));
            float snk = __ldg(&sinks[kvh * 4 + g]);
            m = fmaxf(m, snk);
            float sum = 0.f;
#pragma unroll
            for (int kk = 0; kk < 4; kk++) {
                float e = __expf(s[kk] - m);
                S[r * 129 + lane + kk * 32] = e;
                sum += e;
            }
#pragma unroll
            for (int o = 16; o; o >>= 1)
                sum += __shfl_xor_sync(0xffffffffu, sum, o);
            sum += __expf(snk - m);
            if (lane == 0) den[r] = 1.0f / sum;
        }
    }
    __syncthreads();

    {
        const int b = tid >> 4;
        const int e = tid & 15;
        float o_[4][4];
#pragma unroll
        for (int g = 0; g < 4; g++)
#pragma unroll
            for (int z = 0; z < 4; z++) o_[g][z] = 0.f;

        for (int w = 0; w < 128; w++) {
            float4 v4 = *(const float4*)(V + (b + w) * 64 + e * 4);
#pragma unroll
            for (int g = 0; g < 4; g++) {
                float p = S[(4 * b + g) * 129 + w];
                o_[g][0] += p * v4.x;
                o_[g][1] += p * v4.y;
                o_[g][2] += p * v4.z;
                o_[g][3] += p * v4.w;
            }
        }
        const int t = t0 + b;
#pragma unroll
        for (int g = 0; g < 4; g++) {
            float inv = den[4 * b + g];
            float4 r;
            r.x = o_[g][0] * inv; r.y = o_[g][1] * inv;
            r.z = o_[g][2] * inv; r.w = o_[g][3] * inv;
            *(float4*)(g_attn + (size_t)t * DIMX + (kvh * 4 + g) * 64 + e * 4) = r;
        }
    }
}

// ---------------- host ----------------
extern "C" void kernel_launch(void* const* d_in, const int* in_sizes, int n_in,
                              void* d_out, int out_size)
{
    (void)in_sizes; (void)n_in; (void)out_size;
    const float* x     = (const float*)d_in[0];
    const float* cosT  = (const float*)d_in[1];
    const float* sinT  = (const float*)d_in[2];
    const float* Wqkv  = (const float*)d_in[3];
    const float* bqkv  = (const float*)d_in[4];
    const float* Wo    = (const float*)d_in[5];
    const float* bo    = (const float*)d_in[6];
    const float* sinks = (const float*)d_in[7];
    float* out = (float*)d_out;

    float* qkv = nullptr;
    float* att = nullptr;
    cudaGetSymbolAddress((void**)&qkv, g_qkv);
    cudaGetSymbolAddress((void**)&att, g_attn);

    cudaFuncSetAttribute(gemm_mma_tf32,
                         cudaFuncAttributeMaxDynamicSharedMemorySize, GEMM_SMEM);
    const int attn_smem = ATTN_SMEM_FLOATS * 4;
    cudaFuncSetAttribute(swa_kernel,
                         cudaFuncAttributeMaxDynamicSharedMemorySize, attn_smem);

    // 1) qkv = x @ Wqkv^T + bqkv   (tf32 mma.sync)
    gemm_mma_tf32<<<dim3(QKVC / GBN, T_TOK / GBM), 256, GEMM_SMEM>>>(
        x, Wqkv, bqkv, qkv, QKVC, DIMX);
    // 2) RoPE in-place on q,k
    rope_kernel<<<T_TOK, 256>>>(cosT, sinT);
    // 3) sliding-window attention with sink
    swa_kernel<<<dim3(T_TOK / TQ, NKV), 256, attn_smem>>>(sinks);
    // 4) out = attn @ Wo^T + bo    (tf32 mma.sync)
    gemm_mma_tf32<<<dim3(DIMX / GBN, T_TOK / GBM), 256, GEMM_SMEM>>>(
        att, Wo, bo, out, DIMX, DIMX);
}